// round 16
// baseline (speedup 1.0000x reference)
#include <cuda_runtime.h>
#include <cuda_bf16.h>
#include <math.h>
#include <stdint.h>

#define BS    12288     // 3 * 4096
#define BATCH 4096
#define D     256
#define TINV  10.0f     // 1 / temp

// GEMM tiling (R4 configuration — measured optimum)
#define TM    128
#define TN    128
#define KC    32                 // k-chunk (bf16 elems)
#define NB    (BS / TM)          // 96
#define NPAIR (NB * (NB + 1) / 2)  // 4656 upper-triangular tiles
#define ROWB  80                 // smem row stride in bytes (32 bf16 = 64B + 16B pad)
#define TILEB (128 * ROWB)       // 10240 bytes per staged tile

// Scratch (device globals; no allocation allowed)
__device__ __align__(16) __nv_bfloat16 g_xb[BS * D]; // normalized rows bf16 (GEMM)
__device__ float g_den[BS];                          // masked row sums of exp
__device__ float g_num[3 * BATCH];                   // n12, n13, n23
__device__ unsigned int g_ctr;                       // last-CTA-done counter

__device__ __forceinline__ uint32_t smem_u32(const void* p) {
    uint32_t a;
    asm("{ .reg .u64 t; cvta.to.shared.u64 t, %1; cvt.u32.u64 %0, t; }" : "=r"(a) : "l"(p));
    return a;
}

// ---------------------------------------------------------------------------
// Kernel 1: warp-per-p prep, one warp per CTA. Lane l owns elements
// [8l, 8l+8) of rows {p, B+p, 2B+p}. No smem, no __syncthreads.
// Also resets the last-CTA-done counter (deterministic per launch).
// ---------------------------------------------------------------------------
__global__ __launch_bounds__(32) void k_prep(const float* __restrict__ x) {
    const int lane = threadIdx.x;
    const int p    = blockIdx.x;

    if (p == 0 && lane == 0) g_ctr = 0u;

    const float4* x4 = (const float4*)x;
    float4 a0 = x4[(size_t)p * 64             + 2 * lane];
    float4 a1 = x4[(size_t)p * 64             + 2 * lane + 1];
    float4 b0 = x4[(size_t)(BATCH + p) * 64   + 2 * lane];
    float4 b1 = x4[(size_t)(BATCH + p) * 64   + 2 * lane + 1];
    float4 c0 = x4[(size_t)(2*BATCH + p) * 64 + 2 * lane];
    float4 c1 = x4[(size_t)(2*BATCH + p) * 64 + 2 * lane + 1];

    float s1 = a0.x*a0.x + a0.y*a0.y + a0.z*a0.z + a0.w*a0.w
             + a1.x*a1.x + a1.y*a1.y + a1.z*a1.z + a1.w*a1.w;
    float s2 = b0.x*b0.x + b0.y*b0.y + b0.z*b0.z + b0.w*b0.w
             + b1.x*b1.x + b1.y*b1.y + b1.z*b1.z + b1.w*b1.w;
    float s3 = c0.x*c0.x + c0.y*c0.y + c0.z*c0.z + c0.w*c0.w
             + c1.x*c1.x + c1.y*c1.y + c1.z*c1.z + c1.w*c1.w;
    #pragma unroll
    for (int s = 16; s >= 1; s >>= 1) {
        s1 += __shfl_xor_sync(0xffffffffu, s1, s);
        s2 += __shfl_xor_sync(0xffffffffu, s2, s);
        s3 += __shfl_xor_sync(0xffffffffu, s3, s);
    }

    const float inv1 = 1.0f / fmaxf(sqrtf(s1), 1e-6f);
    const float inv2 = 1.0f / fmaxf(sqrtf(s2), 1e-6f);
    const float inv3 = 1.0f / fmaxf(sqrtf(s3), 1e-6f);

    a0.x *= inv1; a0.y *= inv1; a0.z *= inv1; a0.w *= inv1;
    a1.x *= inv1; a1.y *= inv1; a1.z *= inv1; a1.w *= inv1;
    b0.x *= inv2; b0.y *= inv2; b0.z *= inv2; b0.w *= inv2;
    b1.x *= inv2; b1.y *= inv2; b1.z *= inv2; b1.w *= inv2;
    c0.x *= inv3; c0.y *= inv3; c0.z *= inv3; c0.w *= inv3;
    c1.x *= inv3; c1.y *= inv3; c1.z *= inv3; c1.w *= inv3;

    auto pack8 = [](float4 u, float4 v) {
        union { uint4 q; __nv_bfloat162 h[4]; } r;
        r.h[0] = __float22bfloat162_rn(make_float2(u.x, u.y));
        r.h[1] = __float22bfloat162_rn(make_float2(u.z, u.w));
        r.h[2] = __float22bfloat162_rn(make_float2(v.x, v.y));
        r.h[3] = __float22bfloat162_rn(make_float2(v.z, v.w));
        return r.q;
    };
    uint4* xb4 = (uint4*)g_xb;   // 16B = 8 bf16; row = 32 uint4
    xb4[(size_t)p * 32             + lane] = pack8(a0, a1);
    xb4[(size_t)(BATCH + p) * 32   + lane] = pack8(b0, b1);
    xb4[(size_t)(2*BATCH + p) * 32 + lane] = pack8(c0, c1);

    float d12 = a0.x*b0.x + a0.y*b0.y + a0.z*b0.z + a0.w*b0.w
              + a1.x*b1.x + a1.y*b1.y + a1.z*b1.z + a1.w*b1.w;
    float d13 = a0.x*c0.x + a0.y*c0.y + a0.z*c0.z + a0.w*c0.w
              + a1.x*c1.x + a1.y*c1.y + a1.z*c1.z + a1.w*c1.w;
    float d23 = b0.x*c0.x + b0.y*c0.y + b0.z*c0.z + b0.w*c0.w
              + b1.x*c1.x + b1.y*c1.y + b1.z*c1.z + b1.w*c1.w;
    #pragma unroll
    for (int s = 16; s >= 1; s >>= 1) {
        d12 += __shfl_xor_sync(0xffffffffu, d12, s);
        d13 += __shfl_xor_sync(0xffffffffu, d13, s);
        d23 += __shfl_xor_sync(0xffffffffu, d23, s);
    }
    if (lane == 0) {
        g_num[p]             = expf(d12 * TINV);
        g_num[BATCH + p]     = expf(d13 * TINV);
        g_num[2 * BATCH + p] = expf(d23 * TINV);
        g_den[p] = 0.0f;
        g_den[BATCH + p] = 0.0f;
        g_den[2 * BATCH + p] = 0.0f;
    }
}

// ---------------------------------------------------------------------------
// Kernel 2: symmetric mma.sync bf16 GEMM over upper-triangular 128x128 tiles
// (trunk mainloop, untouched) + last-CTA-done fused finalize.
// ---------------------------------------------------------------------------
__global__ __launch_bounds__(256, 2) void k_den_gemm_mma(float* __restrict__ out) {
    __shared__ __align__(16) uint8_t sm[2][2][TILEB];   // [buf][A/B][tile]
    __shared__ float sden[TM];    // row sums
    __shared__ float sdenc[TN];   // col sums (off-diag only)
    __shared__ unsigned int s_done;
    __shared__ float s_red[8];

    const int tid    = threadIdx.x;
    const int wid    = tid >> 5;
    const int lane   = tid & 31;
    const int warp_m = wid >> 2;      // 0..1
    const int warp_n = wid & 3;       // 0..3

    // --- triangular decode: blockIdx.x -> (bi, bj) with bj >= bi ---
    int bi;
    {
        const int t = blockIdx.x;
        float disc = (NB + 0.5f) * (NB + 0.5f) - 2.0f * (float)t;
        bi = (int)((float)NB + 0.5f - sqrtf(disc));
        while (bi > 0 && t < bi * NB - bi * (bi - 1) / 2) --bi;
        while (t >= (bi + 1) * NB - (bi + 1) * bi / 2) ++bi;
    }
    const int base = bi * NB - bi * (bi - 1) / 2;
    const int bj   = bi + (blockIdx.x - base);
    const int i0   = bi * TM;
    const int j0   = bj * TN;
    const bool offdiag = (bi != bj);

    if (tid < TM) sden[tid] = 0.0f;
    if (tid < TN) sdenc[tid] = 0.0f;

    // ---- cp.async staging: 1024 x 16B per chunk (A: 512, B: 512) ----
    auto stage = [&](int buf, int kc) {
        #pragma unroll
        for (int t = 0; t < 4; ++t) {
            int idx = tid + t * 256;            // 0..1023
            int mat = idx >> 9;                 // 0=A, 1=B
            int r   = (idx >> 2) & 127;
            int seg = idx & 3;                  // 16B segment (8 bf16)
            const __nv_bfloat16* g = g_xb
                + (size_t)((mat ? j0 : i0) + r) * D + kc + seg * 8;
            uint32_t s = smem_u32(&sm[buf][mat][r * ROWB + seg * 16]);
            asm volatile("cp.async.cg.shared.global [%0], [%1], 16;"
                         :: "r"(s), "l"(g));
        }
        asm volatile("cp.async.commit_group;" ::: "memory");
    };

    float acc[4][4][4];
    #pragma unroll
    for (int mf = 0; mf < 4; ++mf)
        #pragma unroll
        for (int nf = 0; nf < 4; ++nf)
            #pragma unroll
            for (int c = 0; c < 4; ++c) acc[mf][nf][c] = 0.0f;

    stage(0, 0);

    #pragma unroll
    for (int ch = 0; ch < D / KC; ++ch) {
        if (ch < D / KC - 1) {
            stage((ch + 1) & 1, (ch + 1) * KC);
            asm volatile("cp.async.wait_group 1;" ::: "memory");
        } else {
            asm volatile("cp.async.wait_group 0;" ::: "memory");
        }
        __syncthreads();

        const uint8_t* A = sm[ch & 1][0];
        const uint8_t* B = sm[ch & 1][1];

        #pragma unroll
        for (int ks = 0; ks < 2; ++ks) {        // two k16 steps per chunk
            uint32_t a[4][4], b[2][4];
            #pragma unroll
            for (int mf = 0; mf < 4; ++mf) {
                int row = warp_m * 64 + mf * 16 + (lane & 15);
                int seg = ks * 2 + (lane >> 4);
                uint32_t addr = smem_u32(A + row * ROWB + seg * 16);
                asm volatile("ldmatrix.sync.aligned.m8n8.x4.shared.b16 "
                             "{%0,%1,%2,%3}, [%4];"
                             : "=r"(a[mf][0]), "=r"(a[mf][1]),
                               "=r"(a[mf][2]), "=r"(a[mf][3])
                             : "r"(addr));
            }
            #pragma unroll
            for (int bh = 0; bh < 2; ++bh) {
                int n   = warp_n * 32 + bh * 16 + ((lane >> 4) << 3) + (lane & 7);
                int seg = ks * 2 + ((lane >> 3) & 1);
                uint32_t addr = smem_u32(B + n * ROWB + seg * 16);
                asm volatile("ldmatrix.sync.aligned.m8n8.x4.shared.b16 "
                             "{%0,%1,%2,%3}, [%4];"
                             : "=r"(b[bh][0]), "=r"(b[bh][1]),
                               "=r"(b[bh][2]), "=r"(b[bh][3])
                             : "r"(addr));
            }
            #pragma unroll
            for (int mf = 0; mf < 4; ++mf) {
                #pragma unroll
                for (int nf = 0; nf < 4; ++nf) {
                    uint32_t b0 = b[nf >> 1][(nf & 1) * 2 + 0];
                    uint32_t b1 = b[nf >> 1][(nf & 1) * 2 + 1];
                    asm volatile(
                        "mma.sync.aligned.m16n8k16.row.col.f32.bf16.bf16.f32 "
                        "{%0,%1,%2,%3}, {%4,%5,%6,%7}, {%8,%9}, {%0,%1,%2,%3};"
                        : "+f"(acc[mf][nf][0]), "+f"(acc[mf][nf][1]),
                          "+f"(acc[mf][nf][2]), "+f"(acc[mf][nf][3])
                        : "r"(a[mf][0]), "r"(a[mf][1]),
                          "r"(a[mf][2]), "r"(a[mf][3]),
                          "r"(b0), "r"(b1));
                }
            }
        }
        __syncthreads();
    }

    // ---- Epilogue: exp once, accumulate row sums (+ col sums if off-diag) ----
    const int r4    = (lane >> 2) & 3;                 // row % 4
    const bool inc0 = ((2 * (lane & 1))     != r4);    // even cols (c0/c2)
    const bool inc1 = ((2 * (lane & 1) + 1) != r4);    // odd  cols (c1/c3)

    float cs[4][2];                                    // col sums per nf (col pair)
    #pragma unroll
    for (int nf = 0; nf < 4; ++nf) { cs[nf][0] = 0.0f; cs[nf][1] = 0.0f; }

    #pragma unroll
    for (int mf = 0; mf < 4; ++mf) {
        float slo = 0.0f, shi = 0.0f;
        #pragma unroll
        for (int nf = 0; nf < 4; ++nf) {
            float e0 = inc0 ? __expf(acc[mf][nf][0] * TINV) : 0.0f;
            float e1 = inc1 ? __expf(acc[mf][nf][1] * TINV) : 0.0f;
            float e2 = inc0 ? __expf(acc[mf][nf][2] * TINV) : 0.0f;
            float e3 = inc1 ? __expf(acc[mf][nf][3] * TINV) : 0.0f;
            slo += e0 + e1;
            shi += e2 + e3;
            cs[nf][0] += e0 + e2;
            cs[nf][1] += e1 + e3;
        }
        // row-sum reduce across the 4 lanes of this row group (lane&3)
        #pragma unroll
        for (int s = 1; s <= 2; s <<= 1) {
            slo += __shfl_xor_sync(0xffffffffu, slo, s);
            shi += __shfl_xor_sync(0xffffffffu, shi, s);
        }
        if ((lane & 3) == 0) {
            int row = warp_m * 64 + mf * 16 + (lane >> 2);
            atomicAdd(&sden[row], slo);
            atomicAdd(&sden[row + 8], shi);
        }
    }

    if (offdiag) {
        // col-sum reduce over rows (lane>>2 axis): xor 4, 8, 16
        #pragma unroll
        for (int nf = 0; nf < 4; ++nf) {
            #pragma unroll
            for (int s = 4; s <= 16; s <<= 1) {
                cs[nf][0] += __shfl_xor_sync(0xffffffffu, cs[nf][0], s);
                cs[nf][1] += __shfl_xor_sync(0xffffffffu, cs[nf][1], s);
            }
        }
        if (lane < 4) {
            #pragma unroll
            for (int nf = 0; nf < 4; ++nf) {
                int col = warp_n * 32 + nf * 8 + 2 * lane;
                atomicAdd(&sdenc[col],     cs[nf][0]);
                atomicAdd(&sdenc[col + 1], cs[nf][1]);
            }
        }
    }

    __syncthreads();
    if (tid < TM) atomicAdd(&g_den[i0 + tid], sden[tid]);
    if (offdiag && tid < TN) atomicAdd(&g_den[j0 + tid], sdenc[tid]);

    // ---- last-CTA-done fused finalize ----
    __threadfence();                       // make this CTA's g_den atomics visible
    __syncthreads();                       // all threads' atomics issued before count
    if (tid == 0)
        s_done = atomicAdd(&g_ctr, 1u);
    __syncthreads();
    if (s_done == NPAIR - 1) {
        __threadfence();                   // acquire: see all other CTAs' g_den
        float local = 0.0f;
        #pragma unroll
        for (int u = 0; u < BATCH / 256; ++u) {
            int p = u * 256 + tid;
            float d1 = g_den[p];
            float d2 = g_den[BATCH + p];
            float d3 = g_den[2 * BATCH + p];
            float n12 = g_num[p];
            float n13 = g_num[BATCH + p];
            float n23 = g_num[2 * BATCH + p];
            local += log1pf(d1 / n12) + log1pf(d2 / n12)
                   + log1pf(d1 / n13) + log1pf(d3 / n13)
                   + log1pf(d2 / n23) + log1pf(d3 / n23);
        }
        #pragma unroll
        for (int s = 16; s >= 1; s >>= 1)
            local += __shfl_xor_sync(0xffffffffu, local, s);
        if (lane == 0) s_red[wid] = local;
        __syncthreads();
        if (tid == 0) {
            float tot = 0.0f;
            #pragma unroll
            for (int u = 0; u < 8; ++u) tot += s_red[u];
            out[0] = tot / (2.0f * (float)BATCH);
        }
    }
}

extern "C" void kernel_launch(void* const* d_in, const int* in_sizes, int n_in,
                              void* d_out, int out_size) {
    const float* reg_pred = (const float*)d_in[0];
    float* out = (float*)d_out;

    k_prep<<<BATCH, 32>>>(reg_pred);
    k_den_gemm_mma<<<NPAIR, 256>>>(out);
}

// round 17
// speedup vs baseline: 1.1955x; 1.1955x over previous
#include <cuda_runtime.h>
#include <cuda_bf16.h>
#include <math.h>
#include <stdint.h>

#define BS    12288     // 3 * 4096
#define BATCH 4096
#define D     256
#define TINV  10.0f     // 1 / temp

// GEMM tiling (R4 configuration — measured optimum)
#define TM    128
#define TN    128
#define KC    32                 // k-chunk (bf16 elems)
#define NB    (BS / TM)          // 96
#define NPAIR (NB * (NB + 1) / 2)  // 4656 upper-triangular tiles
#define ROWB  80                 // smem row stride in bytes (32 bf16 = 64B + 16B pad)
#define TILEB (128 * ROWB)       // 10240 bytes per staged tile

// Scratch (device globals; no allocation allowed)
__device__ __align__(16) __nv_bfloat16 g_xb[BS * D]; // normalized rows bf16 (GEMM)
__device__ float g_den[BS];                          // masked row sums of exp
__device__ float g_num[3 * BATCH];                   // n12, n13, n23

__device__ __forceinline__ uint32_t smem_u32(const void* p) {
    uint32_t a;
    asm("{ .reg .u64 t; cvta.to.shared.u64 t, %1; cvt.u32.u64 %0, t; }" : "=r"(a) : "l"(p));
    return a;
}

// ---------------------------------------------------------------------------
// Kernel 1: warp-per-p prep, one warp per CTA (R15 version, unchanged).
// ---------------------------------------------------------------------------
__global__ __launch_bounds__(32) void k_prep(const float* __restrict__ x,
                                             float* __restrict__ out) {
    const int lane = threadIdx.x;
    const int p    = blockIdx.x;

    if (p == 0 && lane == 0) out[0] = 0.0f;

    const float4* x4 = (const float4*)x;
    float4 a0 = x4[(size_t)p * 64             + 2 * lane];
    float4 a1 = x4[(size_t)p * 64             + 2 * lane + 1];
    float4 b0 = x4[(size_t)(BATCH + p) * 64   + 2 * lane];
    float4 b1 = x4[(size_t)(BATCH + p) * 64   + 2 * lane + 1];
    float4 c0 = x4[(size_t)(2*BATCH + p) * 64 + 2 * lane];
    float4 c1 = x4[(size_t)(2*BATCH + p) * 64 + 2 * lane + 1];

    float s1 = a0.x*a0.x + a0.y*a0.y + a0.z*a0.z + a0.w*a0.w
             + a1.x*a1.x + a1.y*a1.y + a1.z*a1.z + a1.w*a1.w;
    float s2 = b0.x*b0.x + b0.y*b0.y + b0.z*b0.z + b0.w*b0.w
             + b1.x*b1.x + b1.y*b1.y + b1.z*b1.z + b1.w*b1.w;
    float s3 = c0.x*c0.x + c0.y*c0.y + c0.z*c0.z + c0.w*c0.w
             + c1.x*c1.x + c1.y*c1.y + c1.z*c1.z + c1.w*c1.w;
    #pragma unroll
    for (int s = 16; s >= 1; s >>= 1) {
        s1 += __shfl_xor_sync(0xffffffffu, s1, s);
        s2 += __shfl_xor_sync(0xffffffffu, s2, s);
        s3 += __shfl_xor_sync(0xffffffffu, s3, s);
    }

    const float inv1 = 1.0f / fmaxf(sqrtf(s1), 1e-6f);
    const float inv2 = 1.0f / fmaxf(sqrtf(s2), 1e-6f);
    const float inv3 = 1.0f / fmaxf(sqrtf(s3), 1e-6f);

    a0.x *= inv1; a0.y *= inv1; a0.z *= inv1; a0.w *= inv1;
    a1.x *= inv1; a1.y *= inv1; a1.z *= inv1; a1.w *= inv1;
    b0.x *= inv2; b0.y *= inv2; b0.z *= inv2; b0.w *= inv2;
    b1.x *= inv2; b1.y *= inv2; b1.z *= inv2; b1.w *= inv2;
    c0.x *= inv3; c0.y *= inv3; c0.z *= inv3; c0.w *= inv3;
    c1.x *= inv3; c1.y *= inv3; c1.z *= inv3; c1.w *= inv3;

    auto pack8 = [](float4 u, float4 v) {
        union { uint4 q; __nv_bfloat162 h[4]; } r;
        r.h[0] = __float22bfloat162_rn(make_float2(u.x, u.y));
        r.h[1] = __float22bfloat162_rn(make_float2(u.z, u.w));
        r.h[2] = __float22bfloat162_rn(make_float2(v.x, v.y));
        r.h[3] = __float22bfloat162_rn(make_float2(v.z, v.w));
        return r.q;
    };
    uint4* xb4 = (uint4*)g_xb;   // 16B = 8 bf16; row = 32 uint4
    xb4[(size_t)p * 32             + lane] = pack8(a0, a1);
    xb4[(size_t)(BATCH + p) * 32   + lane] = pack8(b0, b1);
    xb4[(size_t)(2*BATCH + p) * 32 + lane] = pack8(c0, c1);

    float d12 = a0.x*b0.x + a0.y*b0.y + a0.z*b0.z + a0.w*b0.w
              + a1.x*b1.x + a1.y*b1.y + a1.z*b1.z + a1.w*b1.w;
    float d13 = a0.x*c0.x + a0.y*c0.y + a0.z*c0.z + a0.w*c0.w
              + a1.x*c1.x + a1.y*c1.y + a1.z*c1.z + a1.w*c1.w;
    float d23 = b0.x*c0.x + b0.y*c0.y + b0.z*c0.z + b0.w*c0.w
              + b1.x*c1.x + b1.y*c1.y + b1.z*c1.z + b1.w*c1.w;
    #pragma unroll
    for (int s = 16; s >= 1; s >>= 1) {
        d12 += __shfl_xor_sync(0xffffffffu, d12, s);
        d13 += __shfl_xor_sync(0xffffffffu, d13, s);
        d23 += __shfl_xor_sync(0xffffffffu, d23, s);
    }
    if (lane == 0) {
        g_num[p]             = expf(d12 * TINV);
        g_num[BATCH + p]     = expf(d13 * TINV);
        g_num[2 * BATCH + p] = expf(d23 * TINV);
        g_den[p] = 0.0f;
        g_den[BATCH + p] = 0.0f;
        g_den[2 * BATCH + p] = 0.0f;
    }
}

// ---------------------------------------------------------------------------
// Kernel 2: symmetric mma.sync bf16 GEMM, trunk schedule, with all ldmatrix
// base addresses HOISTED out of the mainloop (affine in ch,ks: one IADD3 per
// ldmatrix instead of the full row*ROWB+seg*16+cvta recompute).
// ---------------------------------------------------------------------------
__global__ __launch_bounds__(256, 2) void k_den_gemm_mma() {
    __shared__ __align__(16) uint8_t sm[2][2][TILEB];   // [buf][A/B][tile]
    __shared__ float sden[TM];    // row sums
    __shared__ float sdenc[TN];   // col sums (off-diag only)

    const int tid    = threadIdx.x;
    const int wid    = tid >> 5;
    const int lane   = tid & 31;
    const int warp_m = wid >> 2;      // 0..1
    const int warp_n = wid & 3;       // 0..3

    // --- triangular decode: blockIdx.x -> (bi, bj) with bj >= bi ---
    int bi;
    {
        const int t = blockIdx.x;
        float disc = (NB + 0.5f) * (NB + 0.5f) - 2.0f * (float)t;
        bi = (int)((float)NB + 0.5f - sqrtf(disc));
        while (bi > 0 && t < bi * NB - bi * (bi - 1) / 2) --bi;
        while (t >= (bi + 1) * NB - (bi + 1) * bi / 2) ++bi;
    }
    const int base = bi * NB - bi * (bi - 1) / 2;
    const int bj   = bi + (blockIdx.x - base);
    const int i0   = bi * TM;
    const int j0   = bj * TN;
    const bool offdiag = (bi != bj);

    if (tid < TM) sden[tid] = 0.0f;
    if (tid < TN) sdenc[tid] = 0.0f;

    // ---- hoisted ldmatrix base addresses (buf 0; buf 1 adds 2*TILEB) ----
    const uint32_t smBase = smem_u32(&sm[0][0][0]);
    uint32_t aBase[4], bBase[2];
    #pragma unroll
    for (int mf = 0; mf < 4; ++mf)
        aBase[mf] = smBase + (warp_m * 64 + mf * 16 + (lane & 15)) * ROWB
                  + (lane >> 4) * 16;
    #pragma unroll
    for (int bh = 0; bh < 2; ++bh)
        bBase[bh] = smBase + TILEB
                  + (warp_n * 32 + bh * 16 + ((lane >> 4) << 3) + (lane & 7)) * ROWB
                  + ((lane >> 3) & 1) * 16;

    // ---- cp.async staging: 1024 x 16B per chunk (A: 512, B: 512) ----
    auto stage = [&](int buf, int kc) {
        #pragma unroll
        for (int t = 0; t < 4; ++t) {
            int idx = tid + t * 256;            // 0..1023
            int mat = idx >> 9;                 // 0=A, 1=B
            int r   = (idx >> 2) & 127;
            int seg = idx & 3;                  // 16B segment (8 bf16)
            const __nv_bfloat16* g = g_xb
                + (size_t)((mat ? j0 : i0) + r) * D + kc + seg * 8;
            uint32_t s = smem_u32(&sm[buf][mat][r * ROWB + seg * 16]);
            asm volatile("cp.async.cg.shared.global [%0], [%1], 16;"
                         :: "r"(s), "l"(g));
        }
        asm volatile("cp.async.commit_group;" ::: "memory");
    };

    float acc[4][4][4];
    #pragma unroll
    for (int mf = 0; mf < 4; ++mf)
        #pragma unroll
        for (int nf = 0; nf < 4; ++nf)
            #pragma unroll
            for (int c = 0; c < 4; ++c) acc[mf][nf][c] = 0.0f;

    stage(0, 0);

    #pragma unroll
    for (int ch = 0; ch < D / KC; ++ch) {
        if (ch < D / KC - 1) {
            stage((ch + 1) & 1, (ch + 1) * KC);
            asm volatile("cp.async.wait_group 1;" ::: "memory");
        } else {
            asm volatile("cp.async.wait_group 0;" ::: "memory");
        }
        __syncthreads();

        const uint32_t bufOff = (ch & 1) ? (uint32_t)(2 * TILEB) : 0u;

        #pragma unroll
        for (int ks = 0; ks < 2; ++ks) {        // two k16 steps per chunk
            const uint32_t koff = bufOff + ks * 32;
            uint32_t a[4][4], b[2][4];
            #pragma unroll
            for (int mf = 0; mf < 4; ++mf) {
                asm volatile("ldmatrix.sync.aligned.m8n8.x4.shared.b16 "
                             "{%0,%1,%2,%3}, [%4];"
                             : "=r"(a[mf][0]), "=r"(a[mf][1]),
                               "=r"(a[mf][2]), "=r"(a[mf][3])
                             : "r"(aBase[mf] + koff));
            }
            #pragma unroll
            for (int bh = 0; bh < 2; ++bh) {
                asm volatile("ldmatrix.sync.aligned.m8n8.x4.shared.b16 "
                             "{%0,%1,%2,%3}, [%4];"
                             : "=r"(b[bh][0]), "=r"(b[bh][1]),
                               "=r"(b[bh][2]), "=r"(b[bh][3])
                             : "r"(bBase[bh] + koff));
            }
            #pragma unroll
            for (int mf = 0; mf < 4; ++mf) {
                #pragma unroll
                for (int nf = 0; nf < 4; ++nf) {
                    uint32_t b0 = b[nf >> 1][(nf & 1) * 2 + 0];
                    uint32_t b1 = b[nf >> 1][(nf & 1) * 2 + 1];
                    asm volatile(
                        "mma.sync.aligned.m16n8k16.row.col.f32.bf16.bf16.f32 "
                        "{%0,%1,%2,%3}, {%4,%5,%6,%7}, {%8,%9}, {%0,%1,%2,%3};"
                        : "+f"(acc[mf][nf][0]), "+f"(acc[mf][nf][1]),
                          "+f"(acc[mf][nf][2]), "+f"(acc[mf][nf][3])
                        : "r"(a[mf][0]), "r"(a[mf][1]),
                          "r"(a[mf][2]), "r"(a[mf][3]),
                          "r"(b0), "r"(b1));
                }
            }
        }
        __syncthreads();
    }

    // ---- Epilogue: exp once, accumulate row sums (+ col sums if off-diag) ----
    const int r4    = (lane >> 2) & 3;                 // row % 4
    const bool inc0 = ((2 * (lane & 1))     != r4);    // even cols (c0/c2)
    const bool inc1 = ((2 * (lane & 1) + 1) != r4);    // odd  cols (c1/c3)

    float cs[4][2];                                    // col sums per nf (col pair)
    #pragma unroll
    for (int nf = 0; nf < 4; ++nf) { cs[nf][0] = 0.0f; cs[nf][1] = 0.0f; }

    #pragma unroll
    for (int mf = 0; mf < 4; ++mf) {
        float slo = 0.0f, shi = 0.0f;
        #pragma unroll
        for (int nf = 0; nf < 4; ++nf) {
            float e0 = inc0 ? __expf(acc[mf][nf][0] * TINV) : 0.0f;
            float e1 = inc1 ? __expf(acc[mf][nf][1] * TINV) : 0.0f;
            float e2 = inc0 ? __expf(acc[mf][nf][2] * TINV) : 0.0f;
            float e3 = inc1 ? __expf(acc[mf][nf][3] * TINV) : 0.0f;
            slo += e0 + e1;
            shi += e2 + e3;
            cs[nf][0] += e0 + e2;
            cs[nf][1] += e1 + e3;
        }
        // row-sum reduce across the 4 lanes of this row group (lane&3)
        #pragma unroll
        for (int s = 1; s <= 2; s <<= 1) {
            slo += __shfl_xor_sync(0xffffffffu, slo, s);
            shi += __shfl_xor_sync(0xffffffffu, shi, s);
        }
        if ((lane & 3) == 0) {
            int row = warp_m * 64 + mf * 16 + (lane >> 2);
            atomicAdd(&sden[row], slo);
            atomicAdd(&sden[row + 8], shi);
        }
    }

    if (offdiag) {
        // col-sum reduce over rows (lane>>2 axis): xor 4, 8, 16
        #pragma unroll
        for (int nf = 0; nf < 4; ++nf) {
            #pragma unroll
            for (int s = 4; s <= 16; s <<= 1) {
                cs[nf][0] += __shfl_xor_sync(0xffffffffu, cs[nf][0], s);
                cs[nf][1] += __shfl_xor_sync(0xffffffffu, cs[nf][1], s);
            }
        }
        if (lane < 4) {
            #pragma unroll
            for (int nf = 0; nf < 4; ++nf) {
                int col = warp_n * 32 + nf * 8 + 2 * lane;
                atomicAdd(&sdenc[col],     cs[nf][0]);
                atomicAdd(&sdenc[col + 1], cs[nf][1]);
            }
        }
    }

    __syncthreads();
    if (tid < TM) atomicAdd(&g_den[i0 + tid], sden[tid]);
    if (offdiag && tid < TN) atomicAdd(&g_den[j0 + tid], sdenc[tid]);
}

// ---------------------------------------------------------------------------
// Kernel 3: final loss; warp-level reduction, one atomic per warp.
// ---------------------------------------------------------------------------
__global__ __launch_bounds__(256) void k_finalize(float* __restrict__ out) {
    const int tid  = threadIdx.x;
    const int lane = tid & 31;
    const int p    = blockIdx.x * 256 + tid;

    float d1 = g_den[p];
    float d2 = g_den[BATCH + p];
    float d3 = g_den[2 * BATCH + p];
    float n12 = g_num[p];
    float n13 = g_num[BATCH + p];
    float n23 = g_num[2 * BATCH + p];
    float local = log1pf(d1 / n12) + log1pf(d2 / n12)
                + log1pf(d1 / n13) + log1pf(d3 / n13)
                + log1pf(d2 / n23) + log1pf(d3 / n23);

    #pragma unroll
    for (int s = 16; s >= 1; s >>= 1)
        local += __shfl_xor_sync(0xffffffffu, local, s);
    if (lane == 0)
        atomicAdd(out, local / (2.0f * (float)BATCH));
}

extern "C" void kernel_launch(void* const* d_in, const int* in_sizes, int n_in,
                              void* d_out, int out_size) {
    const float* reg_pred = (const float*)d_in[0];
    float* out = (float*)d_out;

    k_prep<<<BATCH, 32>>>(reg_pred, out);
    k_den_gemm_mma<<<NPAIR, 256>>>();
    k_finalize<<<BATCH / 256, 256>>>(out);
}